// round 13
// baseline (speedup 1.0000x reference)
#include <cuda_runtime.h>
#include <cuda_fp16.h>
#include <cstdint>

// DigitCapsules dynamic routing, GB300 sm_103a
// B=256, C=10, I=1152, DI=8, DO=16, 3 routing iterations.
//
// R13: uhat = R4 verbatim (34.3us). route = fused 3-iteration kernel on a
// 4-CTA cluster per batch element (grid 1024, 27 tiles/warp), R4-style
// prefetch, <=64 regs (packed f32x2 state, tiles converted on use) for
// 3 CTAs/SM. Cross-CTA s-reduction: contention-free per-CTA partial slots
// (plain stores, no atomics, no zeroing) + threadfence + cluster.sync.

#define BSZ  256
#define CCL  10
#define ICAP 1152
#define DOV  16
#define DIV  8
#define QSPL 4                 // CTAs per cluster
#define ISL  (ICAP / QSPL)     // 288 capsules per CTA
#define NT   (ISL / 32)        // 9 tiles

typedef unsigned long long ull;

__device__ __align__(256) __half g_uhat[(size_t)BSZ * CCL * ICAP * DOV]; // 94.4 MB
// per-pass partial s: [t][b][q][c][16] floats, contention-free slots
__device__ __align__(256) float g_sp[3 * BSZ * QSPL * CCL * DOV];        // 1.9 MB

// ---------------- packed f32x2 helpers (exact fp32 SIMD-2) ------------------
static __device__ __forceinline__ ull pack2(float x, float y) {
    ull r; asm("mov.b64 %0, {%1, %2};" : "=l"(r) : "f"(x), "f"(y)); return r;
}
static __device__ __forceinline__ void unpack2(ull v, float& x, float& y) {
    asm("mov.b64 {%0, %1}, %2;" : "=f"(x), "=f"(y) : "l"(v));
}
static __device__ __forceinline__ ull fma2(ull a, ull b, ull c) {
    ull d; asm("fma.rn.f32x2 %0, %1, %2, %3;" : "=l"(d) : "l"(a), "l"(b), "l"(c));
    return d;
}
static __device__ __forceinline__ ull mul2(ull a, ull b) {
    ull d; asm("mul.rn.f32x2 %0, %1, %2;" : "=l"(d) : "l"(a), "l"(b)); return d;
}
static __device__ __forceinline__ ull add2(ull a, ull b) {
    ull d; asm("add.rn.f32x2 %0, %1, %2;" : "=l"(d) : "l"(a), "l"(b)); return d;
}
static __device__ __forceinline__ ull h2f2(__half2 h) {
    float2 f = __half22float2(h);
    return pack2(f.x, f.y);
}
static __device__ __forceinline__ unsigned int pack_h2(float a, float b) {
    __half2 h = __floats2half2_rn(a, b);
    return *reinterpret_cast<unsigned int*>(&h);
}
static __device__ __forceinline__ void cluster_barrier() {
    asm volatile("barrier.cluster.arrive.aligned;" ::: "memory");
    asm volatile("barrier.cluster.wait.aligned;"   ::: "memory");
}

// ---------------------------------------------------------------------------
// K_uhat (R4 verbatim, 34.3us): u_hat[b,c,i,:] = W[c,i] @ x[b,i]
// ---------------------------------------------------------------------------
__global__ __launch_bounds__(256) void uhat_kernel(
    const float* __restrict__ x, const float* __restrict__ W)
{
    const int i = blockIdx.x;
    const int b = threadIdx.x;

    __shared__ float4 Ws[CCL * DOV * 2];   // 5120 B

    for (int f = threadIdx.x; f < CCL * DOV * 2; f += 256) {
        int c = f >> 5, rem = f & 31, d = rem >> 1, h = rem & 1;
        Ws[f] = *reinterpret_cast<const float4*>(
            W + ((((size_t)c * ICAP + i) * DOV) + d) * DIV + h * 4);
    }

    const float* xp = x + (size_t)b * (ICAP * DIV) + (size_t)i * DIV;
    const float4 x0 = *reinterpret_cast<const float4*>(xp);
    const float4 x1 = *reinterpret_cast<const float4*>(xp + 4);

    __syncthreads();

    __half* up = g_uhat + (size_t)b * (CCL * ICAP * DOV) + (size_t)i * DOV;

    #pragma unroll
    for (int c = 0; c < CCL; c++) {
        float r[DOV];
        #pragma unroll
        for (int d = 0; d < DOV; d++) {
            float4 w0 = Ws[c * 32 + d * 2];
            float4 w1 = Ws[c * 32 + d * 2 + 1];
            float v = w0.x * x0.x;
            v = fmaf(w0.y, x0.y, v); v = fmaf(w0.z, x0.z, v); v = fmaf(w0.w, x0.w, v);
            v = fmaf(w1.x, x1.x, v); v = fmaf(w1.y, x1.y, v);
            v = fmaf(w1.z, x1.z, v); v = fmaf(w1.w, x1.w, v);
            r[d] = v;
        }
        uint4 q0, q1;
        q0.x = pack_h2(r[0],  r[1]);  q0.y = pack_h2(r[2],  r[3]);
        q0.z = pack_h2(r[4],  r[5]);  q0.w = pack_h2(r[6],  r[7]);
        q1.x = pack_h2(r[8],  r[9]);  q1.y = pack_h2(r[10], r[11]);
        q1.z = pack_h2(r[12], r[13]); q1.w = pack_h2(r[14], r[15]);
        __half* o = up + (size_t)c * (ICAP * DOV);
        *reinterpret_cast<uint4*>(o)     = q0;
        *reinterpret_cast<uint4*>(o + 8) = q1;
    }
}

// ---------------------------------------------------------------------------
// route_kernel: 4-CTA cluster per b; grid = 1024; 320 thr: warp=class, lane=i.
// 9 tiles per pass, prefetched. Packed f32x2 state, tiles converted on use.
// ---------------------------------------------------------------------------
__global__ void __cluster_dims__(QSPL, 1, 1) __launch_bounds__(320, 3)
route_kernel(float* __restrict__ out)
{
    const int b  = blockIdx.x >> 2;
    const int q  = blockIdx.x & (QSPL - 1);
    const int c  = threadIdx.x >> 5;
    const int ii = threadIdx.x & 31;

    __shared__ float e_s[2][CCL][33];

    const __half* ub = g_uhat + ((size_t)b * CCL + c) * (size_t)ICAP * DOV
                              + (size_t)(q * ISL + ii) * DOV;

    ull vrp[8];    // packed vacc
    ull sacp[8];   // packed partial s

    #pragma unroll 1
    for (int t = 0; t < 3; t++) {
        #pragma unroll
        for (int j = 0; j < 8; j++) sacp[j] = 0ULL;

        // prime the prefetch
        const uint4* p0 = reinterpret_cast<const uint4*>(ub);
        uint4 ca = p0[0], cb = p0[1];

        if (t == 0) {
            const ull w2 = pack2(0.1f, 0.1f);   // softmax of zeros over 10
            for (int ti = 0; ti < NT; ti++) {
                const int tn = (ti + 1 < NT) ? (ti + 1) : (NT - 1);
                const uint4* pn = reinterpret_cast<const uint4*>(
                    ub + (size_t)tn * 32 * DOV);
                uint4 na = pn[0], nb = pn[1];

                const __half2* ha = reinterpret_cast<const __half2*>(&ca);
                const __half2* hb = reinterpret_cast<const __half2*>(&cb);
                #pragma unroll
                for (int k = 0; k < 4; k++) sacp[k]     = fma2(w2, h2f2(ha[k]), sacp[k]);
                #pragma unroll
                for (int k = 0; k < 4; k++) sacp[4 + k] = fma2(w2, h2f2(hb[k]), sacp[4 + k]);

                ca = na; cb = nb;
            }
        } else {
            for (int ti = 0; ti < NT; ti++) {
                const int tn = (ti + 1 < NT) ? (ti + 1) : (NT - 1);
                const uint4* pn = reinterpret_cast<const uint4*>(
                    ub + (size_t)tn * 32 * DOV);
                uint4 na = pn[0], nb = pn[1];

                const __half2* ha = reinterpret_cast<const __half2*>(&ca);
                const __half2* hb = reinterpret_cast<const __half2*>(&cb);

                // dot <u, vacc>: convert-and-consume (no persistent unpacked u)
                ull d0 = mul2(h2f2(ha[0]), vrp[0]);
                ull d1 = mul2(h2f2(ha[1]), vrp[1]);
                d0 = fma2(h2f2(ha[2]), vrp[2], d0);
                d1 = fma2(h2f2(ha[3]), vrp[3], d1);
                d0 = fma2(h2f2(hb[0]), vrp[4], d0);
                d1 = fma2(h2f2(hb[1]), vrp[5], d1);
                d0 = fma2(h2f2(hb[2]), vrp[6], d0);
                d1 = fma2(h2f2(hb[3]), vrp[7], d1);
                d0 = add2(d0, d1);
                float lo, hi; unpack2(d0, lo, hi);

                // |logit| bounded (~35): exp safe in fp32 without max-subtract
                const int pb = ti & 1;
                e_s[pb][c][ii] = __expf(lo + hi);
                __syncthreads();

                float Z = e_s[pb][0][ii];
                #pragma unroll
                for (int cc = 1; cc < CCL; cc++) Z += e_s[pb][cc][ii];
                float w = __fdividef(e_s[pb][c][ii], Z);
                ull w2 = pack2(w, w);

                #pragma unroll
                for (int k = 0; k < 4; k++) sacp[k]     = fma2(w2, h2f2(ha[k]), sacp[k]);
                #pragma unroll
                for (int k = 0; k < 4; k++) sacp[4 + k] = fma2(w2, h2f2(hb[k]), sacp[4 + k]);

                ca = na; cb = nb;
            }
        }

        // butterfly reduce over 32 lanes (packed: shfl the two halves)
        float sac[DOV];
        #pragma unroll
        for (int j = 0; j < 8; j++) unpack2(sacp[j], sac[2 * j], sac[2 * j + 1]);
        #pragma unroll
        for (int off = 16; off > 0; off >>= 1)
            #pragma unroll
            for (int j = 0; j < DOV; j++)
                sac[j] += __shfl_xor_sync(0xffffffffu, sac[j], off);

        // write this CTA's partial s to its private slot (no atomics)
        float* sp = g_sp + ((((size_t)t * BSZ + b) * QSPL + q) * CCL + c) * DOV;
        if (ii == 0) {
            float4* spv = reinterpret_cast<float4*>(sp);
            spv[0] = make_float4(sac[0],  sac[1],  sac[2],  sac[3]);
            spv[1] = make_float4(sac[4],  sac[5],  sac[6],  sac[7]);
            spv[2] = make_float4(sac[8],  sac[9],  sac[10], sac[11]);
            spv[3] = make_float4(sac[12], sac[13], sac[14], sac[15]);
            __threadfence();
        }
        cluster_barrier();   // all 4 partials visible

        // sum the 4 partials + squash (identical in every CTA)
        float s[DOV];
        {
            const float* base = g_sp + (((size_t)t * BSZ + b) * QSPL) * CCL * DOV
                              + (size_t)c * DOV;
            #pragma unroll
            for (int j = 0; j < DOV; j++) s[j] = __ldcg(base + j);
            #pragma unroll
            for (int qq = 1; qq < QSPL; qq++) {
                const float* pq = base + (size_t)qq * CCL * DOV;
                #pragma unroll
                for (int j = 0; j < DOV; j++) s[j] += __ldcg(pq + j);
            }
        }
        float sq = 0.0f;
        #pragma unroll
        for (int j = 0; j < DOV; j++) sq = fmaf(s[j], s[j], sq);
        float scale = __fdividef(sqrtf(sq), 1.0f + sq);

        if (t == 2) {
            if (q == 0 && ii == 0) {
                float4* op = reinterpret_cast<float4*>(
                    out + ((size_t)b * CCL + c) * DOV);
                op[0] = make_float4(s[0]*scale,  s[1]*scale,  s[2]*scale,  s[3]*scale);
                op[1] = make_float4(s[4]*scale,  s[5]*scale,  s[6]*scale,  s[7]*scale);
                op[2] = make_float4(s[8]*scale,  s[9]*scale,  s[10]*scale, s[11]*scale);
                op[3] = make_float4(s[12]*scale, s[13]*scale, s[14]*scale, s[15]*scale);
            }
        } else if (t == 0) {
            #pragma unroll
            for (int j = 0; j < 8; j++)
                vrp[j] = pack2(s[2 * j] * scale, s[2 * j + 1] * scale);
        } else {
            float v0, v1;
            #pragma unroll
            for (int j = 0; j < 8; j++) {
                unpack2(vrp[j], v0, v1);
                vrp[j] = pack2(fmaf(s[2 * j], scale, v0),
                               fmaf(s[2 * j + 1], scale, v1));
            }
        }
    }
}

// ---------------------------------------------------------------------------
extern "C" void kernel_launch(void* const* d_in, const int* in_sizes, int n_in,
                              void* d_out, int out_size)
{
    const float* x = (const float*)d_in[0];
    const float* W = (const float*)d_in[1];
    if (in_sizes[0] == CCL * ICAP * DOV * DIV) {  // defensively identify by size
        const float* t = x; x = W; W = t;
    }
    float* out = (float*)d_out;

    uhat_kernel<<<ICAP, 256>>>(x, W);
    route_kernel<<<BSZ * QSPL, 320>>>(out);
}

// round 14
// speedup vs baseline: 1.2552x; 1.2552x over previous
#include <cuda_runtime.h>
#include <cuda_fp16.h>
#include <cstdint>

// DigitCapsules dynamic routing, GB300 sm_103a
// B=256, C=10, I=1152, DI=8, DO=16, 3 routing iterations.
//
// R14: uhat = R4 verbatim. route = R4 team structure, but TWO independent
// 10-warp teams per block (team = batch element), named barriers per team.
// Fixes the SMSP imbalance that pinned route at ~52us: 20 warps/block =
// 5/5/5/5 per SMSP (was 3/3/2/2 x2 = 6/6/4/4 on two-block SMs), grid 128 =
// one block per SM, single wave, no cross-team convoy.

#define BSZ  256
#define CCL  10
#define ICAP 1152
#define DOV  16
#define DIV  8
#define NT   (ICAP / 32)   // 36 tiles of 32 capsules

__device__ __align__(256) __half g_uhat[(size_t)BSZ * CCL * ICAP * DOV]; // 94.4 MB

static __device__ __forceinline__ unsigned int pack_h2(float a, float b) {
    __half2 h = __floats2half2_rn(a, b);
    return *reinterpret_cast<unsigned int*>(&h);
}

// ---------------------------------------------------------------------------
// K_uhat (R4 verbatim, 34.3us): u_hat[b,c,i,:] = W[c,i] @ x[b,i]
// grid = I (block per input capsule), 256 threads = b.
// ---------------------------------------------------------------------------
__global__ __launch_bounds__(256) void uhat_kernel(
    const float* __restrict__ x, const float* __restrict__ W)
{
    const int i = blockIdx.x;
    const int b = threadIdx.x;

    __shared__ float4 Ws[CCL * DOV * 2];   // 5120 B

    for (int f = threadIdx.x; f < CCL * DOV * 2; f += 256) {
        int c = f >> 5, rem = f & 31, d = rem >> 1, h = rem & 1;
        Ws[f] = *reinterpret_cast<const float4*>(
            W + ((((size_t)c * ICAP + i) * DOV) + d) * DIV + h * 4);
    }

    const float* xp = x + (size_t)b * (ICAP * DIV) + (size_t)i * DIV;
    const float4 x0 = *reinterpret_cast<const float4*>(xp);
    const float4 x1 = *reinterpret_cast<const float4*>(xp + 4);

    __syncthreads();

    __half* up = g_uhat + (size_t)b * (CCL * ICAP * DOV) + (size_t)i * DOV;

    #pragma unroll
    for (int c = 0; c < CCL; c++) {
        float r[DOV];
        #pragma unroll
        for (int d = 0; d < DOV; d++) {
            float4 w0 = Ws[c * 32 + d * 2];
            float4 w1 = Ws[c * 32 + d * 2 + 1];
            float v = w0.x * x0.x;
            v = fmaf(w0.y, x0.y, v); v = fmaf(w0.z, x0.z, v); v = fmaf(w0.w, x0.w, v);
            v = fmaf(w1.x, x1.x, v); v = fmaf(w1.y, x1.y, v);
            v = fmaf(w1.z, x1.z, v); v = fmaf(w1.w, x1.w, v);
            r[d] = v;
        }
        uint4 q0, q1;
        q0.x = pack_h2(r[0],  r[1]);  q0.y = pack_h2(r[2],  r[3]);
        q0.z = pack_h2(r[4],  r[5]);  q0.w = pack_h2(r[6],  r[7]);
        q1.x = pack_h2(r[8],  r[9]);  q1.y = pack_h2(r[10], r[11]);
        q1.z = pack_h2(r[12], r[13]); q1.w = pack_h2(r[14], r[15]);
        __half* o = up + (size_t)c * (ICAP * DOV);
        *reinterpret_cast<uint4*>(o)     = q0;
        *reinterpret_cast<uint4*>(o + 8) = q1;
    }
}

// unpack one capsule (2x uint4 of half2) into 16 floats
static __device__ __forceinline__ void unpack16(const uint4& a, const uint4& b,
                                                float* __restrict__ u) {
    const __half2* ha = reinterpret_cast<const __half2*>(&a);
    const __half2* hb = reinterpret_cast<const __half2*>(&b);
    #pragma unroll
    for (int q = 0; q < 4; q++) {
        float2 f = __half22float2(ha[q]);
        u[q * 2] = f.x; u[q * 2 + 1] = f.y;
    }
    #pragma unroll
    for (int q = 0; q < 4; q++) {
        float2 f = __half22float2(hb[q]);
        u[8 + q * 2] = f.x; u[8 + q * 2 + 1] = f.y;
    }
}

// named barrier for one 320-thread team (id 1 or 2)
static __device__ __forceinline__ void team_bar(int id) {
    asm volatile("bar.sync %0, 320;" :: "r"(id) : "memory");
}

// ---------------------------------------------------------------------------
// route_kernel: grid = B/2 = 128 blocks, 640 threads = 2 independent teams.
// Team tm (warps 10tm..10tm+9) routes batch element b = 2*blockIdx.x + tm,
// R4 inner structure verbatim, team-scoped named barriers.
// ---------------------------------------------------------------------------
__global__ __launch_bounds__(640, 1) void route_kernel(float* __restrict__ out)
{
    const int wid = threadIdx.x >> 5;          // 0..19
    const int tm  = (wid >= CCL) ? 1 : 0;      // team
    const int c   = wid - tm * CCL;            // class 0..9
    const int ii  = threadIdx.x & 31;          // lane = capsule slot
    const int b   = blockIdx.x * 2 + tm;
    const int bar = 1 + tm;                    // named barrier id

    __shared__ float e_s[2][2][CCL][33];       // [team][parity][c][i]

    const __half* ub = g_uhat + ((size_t)b * CCL + c) * (size_t)ICAP * DOV;

    float vr[DOV];
    #pragma unroll
    for (int j = 0; j < DOV; j++) vr[j] = 0.0f;

    float sac[DOV];

    // ---------------- iteration 0: uniform weights 0.1, no barriers
    #pragma unroll
    for (int j = 0; j < DOV; j++) sac[j] = 0.0f;
    {
        const uint4* p0 = reinterpret_cast<const uint4*>(ub + (size_t)ii * DOV);
        uint4 ua = p0[0], ux = p0[1];
        for (int ti = 0; ti < NT; ti++) {
            const int tn = (ti + 1 < NT) ? (ti + 1) : (NT - 1);
            const uint4* pn = reinterpret_cast<const uint4*>(
                ub + (size_t)(tn * 32 + ii) * DOV);
            uint4 na = pn[0], nb = pn[1];

            float u[DOV];
            unpack16(ua, ux, u);
            #pragma unroll
            for (int j = 0; j < DOV; j++) sac[j] = fmaf(0.1f, u[j], sac[j]);

            ua = na; ux = nb;
        }
    }
    #pragma unroll
    for (int off = 16; off > 0; off >>= 1)
        #pragma unroll
        for (int j = 0; j < DOV; j++)
            sac[j] += __shfl_xor_sync(0xffffffffu, sac[j], off);
    {
        float sq = 0.0f;
        #pragma unroll
        for (int j = 0; j < DOV; j++) sq = fmaf(sac[j], sac[j], sq);
        float scale = __fdividef(sqrtf(sq), 1.0f + sq);
        #pragma unroll
        for (int j = 0; j < DOV; j++) vr[j] = sac[j] * scale;
    }

    // ---------------- iterations 1 and 2
    #pragma unroll 1
    for (int t = 1; t < 3; t++) {
        #pragma unroll
        for (int j = 0; j < DOV; j++) sac[j] = 0.0f;

        const uint4* p0 = reinterpret_cast<const uint4*>(ub + (size_t)ii * DOV);
        uint4 ua = p0[0], ux = p0[1];

        for (int ti = 0; ti < NT; ti++) {
            const int tn = (ti + 1 < NT) ? (ti + 1) : (NT - 1);
            const uint4* pn = reinterpret_cast<const uint4*>(
                ub + (size_t)(tn * 32 + ii) * DOV);
            uint4 na = pn[0], nb = pn[1];

            float u[DOV];
            unpack16(ua, ux, u);

            float a = u[0] * vr[0];
            #pragma unroll
            for (int j = 1; j < DOV; j++) a = fmaf(u[j], vr[j], a);
            // |logit| bounded (~35): exp safe in fp32 without max-subtract
            float e = __expf(a);
            const int pb = ti & 1;
            e_s[tm][pb][c][ii] = e;
            team_bar(bar);
            float Z = e_s[tm][pb][0][ii];
            #pragma unroll
            for (int cc = 1; cc < CCL; cc++) Z += e_s[tm][pb][cc][ii];
            float w = __fdividef(e, Z);

            #pragma unroll
            for (int j = 0; j < DOV; j++) sac[j] = fmaf(w, u[j], sac[j]);

            ua = na; ux = nb;
        }

        #pragma unroll
        for (int off = 16; off > 0; off >>= 1)
            #pragma unroll
            for (int j = 0; j < DOV; j++)
                sac[j] += __shfl_xor_sync(0xffffffffu, sac[j], off);

        float sq = 0.0f;
        #pragma unroll
        for (int j = 0; j < DOV; j++) sq = fmaf(sac[j], sac[j], sq);
        float scale = __fdividef(sqrtf(sq), 1.0f + sq);

        if (t == 2) {
            if (ii == 0) {
                float4* op = reinterpret_cast<float4*>(
                    out + ((size_t)b * CCL + c) * DOV);
                op[0] = make_float4(sac[0]*scale,  sac[1]*scale,  sac[2]*scale,  sac[3]*scale);
                op[1] = make_float4(sac[4]*scale,  sac[5]*scale,  sac[6]*scale,  sac[7]*scale);
                op[2] = make_float4(sac[8]*scale,  sac[9]*scale,  sac[10]*scale, sac[11]*scale);
                op[3] = make_float4(sac[12]*scale, sac[13]*scale, sac[14]*scale, sac[15]*scale);
            }
        } else {
            #pragma unroll
            for (int j = 0; j < DOV; j++) vr[j] += sac[j] * scale;
        }
    }
}

// ---------------------------------------------------------------------------
extern "C" void kernel_launch(void* const* d_in, const int* in_sizes, int n_in,
                              void* d_out, int out_size)
{
    const float* x = (const float*)d_in[0];
    const float* W = (const float*)d_in[1];
    if (in_sizes[0] == CCL * ICAP * DOV * DIV) {  // defensively identify by size
        const float* t = x; x = W; W = t;
    }
    float* out = (float*)d_out;

    uhat_kernel<<<ICAP, 256>>>(x, W);
    route_kernel<<<BSZ / 2, 640>>>(out);
}

// round 15
// speedup vs baseline: 1.2929x; 1.0300x over previous
#include <cuda_runtime.h>
#include <cuda_fp16.h>
#include <cstdint>

// DigitCapsules dynamic routing, GB300 sm_103a
// B=256, C=10, I=1152, DI=8, DO=16, 3 routing iterations.
//
// R15: route = R4 verbatim (proven 51.7us floor). uhat rebuilt:
//   block = (16-i tile, 32-b chunk), grid = 576, 256 threads = (b-pair, i).
//   Warp lanes = 16 consecutive i -> direct STG.128 hits 512B-contiguous runs
//   (8 lines/request vs 32 in R4 -> 4x fewer store wavefronts, no staging).
//   W tile transposed in smem [i][k][d] (padded: k-stride 20, i-stride 164
//   floats -> conflict-free fill, 2-way compute reads), FFMA2 over d-pairs
//   (halves FMA-pipe work). k-accumulation order identical to R4 ->
//   bit-identical u_hat, rel_err unchanged.

#define BSZ  256
#define CCL  10
#define ICAP 1152
#define DOV  16
#define DIV  8
#define NT   (ICAP / 32)   // route: 36 tiles of 32 capsules

#define ITILE 16           // i's per uhat block
#define BCH   32           // b's per uhat block
#define KSTR  20           // Wst k-stride (floats): conflict-free fill
#define ISTR  164          // Wst i-stride (floats): 16B-aligned, 2-way reads

typedef unsigned long long ull;

__device__ __align__(256) __half g_uhat[(size_t)BSZ * CCL * ICAP * DOV]; // 94.4 MB

// ---------------- packed f32x2 helpers (exact fp32 SIMD-2) ------------------
static __device__ __forceinline__ ull pack2(float x, float y) {
    ull r; asm("mov.b64 %0, {%1, %2};" : "=l"(r) : "f"(x), "f"(y)); return r;
}
static __device__ __forceinline__ void unpack2(ull v, float& x, float& y) {
    asm("mov.b64 {%0, %1}, %2;" : "=f"(x), "=f"(y) : "l"(v));
}
static __device__ __forceinline__ ull fma2(ull a, ull b, ull c) {
    ull d; asm("fma.rn.f32x2 %0, %1, %2, %3;" : "=l"(d) : "l"(a), "l"(b), "l"(c));
    return d;
}
static __device__ __forceinline__ unsigned int pack_h2(float a, float b) {
    __half2 h = __floats2half2_rn(a, b);
    return *reinterpret_cast<unsigned int*>(&h);
}

// ---------------------------------------------------------------------------
// K_uhat v3: u_hat[b,c,i,do] = sum_k W[c,i,0,do,k] * x[b,i,k]  (fp32 -> fp16)
// grid = 576 (72 i-tiles x 8 b-chunks, i-tile major for W L2 reuse).
// 256 threads: bg = t>>4 (b-pair index), i = t&15.
// ---------------------------------------------------------------------------
__global__ __launch_bounds__(256) void uhat_kernel(
    const float* __restrict__ x, const float* __restrict__ W)
{
    __shared__ float Wst[ITILE * ISTR];   // [i][k][d] padded: 10496 B

    const int i0 = (blockIdx.x >> 3) * ITILE;
    const int b0 = (blockIdx.x & 7) * BCH;
    const int t  = threadIdx.x;
    const int bg = t >> 4;                // 0..15 (pair of b's)
    const int i  = t & 15;                // i within tile
    const int gi = i0 + i;
    const int bA = b0 + 2 * bg;           // this thread's two b's: bA, bA+1

    // x rows for (bA, gi) and (bA+1, gi): 8 floats each, kept in registers.
    float xr[2][8];
    #pragma unroll
    for (int p = 0; p < 2; p++) {
        const float4* xp = reinterpret_cast<const float4*>(
            x + (size_t)(bA + p) * (ICAP * DIV) + (size_t)gi * DIV);
        float4 a = xp[0], bq = xp[1];
        xr[p][0] = a.x;  xr[p][1] = a.y;  xr[p][2] = a.z;  xr[p][3] = a.w;
        xr[p][4] = bq.x; xr[p][5] = bq.y; xr[p][6] = bq.z; xr[p][7] = bq.w;
    }

    #pragma unroll 1
    for (int c = 0; c < CCL; c++) {
        __syncthreads();   // previous iteration's Wst readers are done
        // fill Wst transposed: src W[c, i0+ie, 0, d, k] (2048 consecutive floats)
        for (int e = t; e < ITILE * DOV * DIV; e += 256) {
            int ie = e >> 7;             // 0..15
            int dk = e & 127;            // d*8 + k (native order)
            int d  = dk >> 3, k = dk & 7;
            Wst[ie * ISTR + k * KSTR + d] =
                W[(size_t)c * (ICAP * DOV * DIV) + (size_t)(i0 + ie) * 128 + dk];
        }
        __syncthreads();

        #pragma unroll
        for (int p = 0; p < 2; p++) {
            ull acc[8];
            #pragma unroll
            for (int j = 0; j < 8; j++) acc[j] = 0ULL;  // {0.f, 0.f}

            #pragma unroll
            for (int k = 0; k < DIV; k++) {
                const ull xx = pack2(xr[p][k], xr[p][k]);
                const ull* wk = reinterpret_cast<const ull*>(
                    Wst + i * ISTR + k * KSTR);
                #pragma unroll
                for (int j = 0; j < 8; j++) acc[j] = fma2(wk[j], xx, acc[j]);
            }

            unsigned int h[8];
            #pragma unroll
            for (int j = 0; j < 8; j++) {
                float lo, hi; unpack2(acc[j], lo, hi);
                h[j] = pack_h2(lo, hi);
            }
            // direct store: warp lanes = 16 consecutive i -> 512B runs
            __half* o = g_uhat
                + (((size_t)(bA + p) * CCL + c) * ICAP + gi) * DOV;
            *reinterpret_cast<uint4*>(o)     = make_uint4(h[0], h[1], h[2], h[3]);
            *reinterpret_cast<uint4*>(o + 8) = make_uint4(h[4], h[5], h[6], h[7]);
        }
    }
}

// ---------------------------------------------------------------------------
// route_kernel: R4 version VERBATIM (51.7us, the measured floor).
// grid = B, 320 threads: warp = class, lane = i slot. 36 tiles, prefetch,
// double-buffered e_s, vacc in warp registers.
// ---------------------------------------------------------------------------
static __device__ __forceinline__ void unpack16(const uint4& a, const uint4& b,
                                                float* __restrict__ u) {
    const __half2* ha = reinterpret_cast<const __half2*>(&a);
    const __half2* hb = reinterpret_cast<const __half2*>(&b);
    #pragma unroll
    for (int q = 0; q < 4; q++) {
        float2 f = __half22float2(ha[q]);
        u[q * 2] = f.x; u[q * 2 + 1] = f.y;
    }
    #pragma unroll
    for (int q = 0; q < 4; q++) {
        float2 f = __half22float2(hb[q]);
        u[8 + q * 2] = f.x; u[8 + q * 2 + 1] = f.y;
    }
}

__global__ __launch_bounds__(320, 2) void route_kernel(float* __restrict__ out)
{
    const int b  = blockIdx.x;
    const int c  = threadIdx.x >> 5;
    const int ii = threadIdx.x & 31;

    __shared__ float e_s[2][CCL][33];

    const __half* ub = g_uhat + ((size_t)b * CCL + c) * (size_t)ICAP * DOV;

    float vr[DOV];
    #pragma unroll
    for (int j = 0; j < DOV; j++) vr[j] = 0.0f;

    float sac[DOV];

    // ---------------- iteration 0: uniform weights 0.1, no barriers
    #pragma unroll
    for (int j = 0; j < DOV; j++) sac[j] = 0.0f;
    {
        const uint4* p0 = reinterpret_cast<const uint4*>(ub + (size_t)ii * DOV);
        uint4 ua = p0[0], ux = p0[1];
        for (int ti = 0; ti < NT; ti++) {
            const int tn = (ti + 1 < NT) ? (ti + 1) : (NT - 1);
            const uint4* pn = reinterpret_cast<const uint4*>(
                ub + (size_t)(tn * 32 + ii) * DOV);
            uint4 na = pn[0], nb = pn[1];

            float u[DOV];
            unpack16(ua, ux, u);
            #pragma unroll
            for (int j = 0; j < DOV; j++) sac[j] = fmaf(0.1f, u[j], sac[j]);

            ua = na; ux = nb;
        }
    }
    #pragma unroll
    for (int off = 16; off > 0; off >>= 1)
        #pragma unroll
        for (int j = 0; j < DOV; j++)
            sac[j] += __shfl_xor_sync(0xffffffffu, sac[j], off);
    {
        float sq = 0.0f;
        #pragma unroll
        for (int j = 0; j < DOV; j++) sq = fmaf(sac[j], sac[j], sq);
        float scale = __fdividef(sqrtf(sq), 1.0f + sq);
        #pragma unroll
        for (int j = 0; j < DOV; j++) vr[j] = sac[j] * scale;
    }

    // ---------------- iterations 1 and 2
    #pragma unroll 1
    for (int t = 1; t < 3; t++) {
        #pragma unroll
        for (int j = 0; j < DOV; j++) sac[j] = 0.0f;

        const uint4* p0 = reinterpret_cast<const uint4*>(ub + (size_t)ii * DOV);
        uint4 ua = p0[0], ux = p0[1];

        for (int ti = 0; ti < NT; ti++) {
            const int tn = (ti + 1 < NT) ? (ti + 1) : (NT - 1);
            const uint4* pn = reinterpret_cast<const uint4*>(
                ub + (size_t)(tn * 32 + ii) * DOV);
            uint4 na = pn[0], nb = pn[1];

            float u[DOV];
            unpack16(ua, ux, u);

            float a = u[0] * vr[0];
            #pragma unroll
            for (int j = 1; j < DOV; j++) a = fmaf(u[j], vr[j], a);
            // |logit| bounded (~35): exp safe in fp32 without max-subtract
            float e = __expf(a);
            const int pb = ti & 1;
            e_s[pb][c][ii] = e;
            __syncthreads();
            float Z = e_s[pb][0][ii];
            #pragma unroll
            for (int cc = 1; cc < CCL; cc++) Z += e_s[pb][cc][ii];
            float w = __fdividef(e, Z);

            #pragma unroll
            for (int j = 0; j < DOV; j++) sac[j] = fmaf(w, u[j], sac[j]);

            ua = na; ux = nb;
        }

        #pragma unroll
        for (int off = 16; off > 0; off >>= 1)
            #pragma unroll
            for (int j = 0; j < DOV; j++)
                sac[j] += __shfl_xor_sync(0xffffffffu, sac[j], off);

        float sq = 0.0f;
        #pragma unroll
        for (int j = 0; j < DOV; j++) sq = fmaf(sac[j], sac[j], sq);
        float scale = __fdividef(sqrtf(sq), 1.0f + sq);

        if (t == 2) {
            if (ii == 0) {
                float4* op = reinterpret_cast<float4*>(
                    out + ((size_t)b * CCL + c) * DOV);
                op[0] = make_float4(sac[0]*scale,  sac[1]*scale,  sac[2]*scale,  sac[3]*scale);
                op[1] = make_float4(sac[4]*scale,  sac[5]*scale,  sac[6]*scale,  sac[7]*scale);
                op[2] = make_float4(sac[8]*scale,  sac[9]*scale,  sac[10]*scale, sac[11]*scale);
                op[3] = make_float4(sac[12]*scale, sac[13]*scale, sac[14]*scale, sac[15]*scale);
            }
        } else {
            #pragma unroll
            for (int j = 0; j < DOV; j++) vr[j] += sac[j] * scale;
        }
    }
}

// ---------------------------------------------------------------------------
extern "C" void kernel_launch(void* const* d_in, const int* in_sizes, int n_in,
                              void* d_out, int out_size)
{
    const float* x = (const float*)d_in[0];
    const float* W = (const float*)d_in[1];
    if (in_sizes[0] == CCL * ICAP * DOV * DIV) {  // defensively identify by size
        const float* t = x; x = W; W = t;
    }
    float* out = (float*)d_out;

    uhat_kernel<<<(ICAP / ITILE) * (BSZ / BCH), 256>>>(x, W);
    route_kernel<<<BSZ, 320>>>(out);
}